// round 6
// baseline (speedup 1.0000x reference)
#include <cuda_runtime.h>
#include <cooperative_groups.h>
namespace cg = cooperative_groups;

#define THETA 0.5f
#define EPS   1e-5f

__device__ __forceinline__ float fast_tanh(float x) {
    float y;
    asm("tanh.approx.f32 %0, %1;" : "=f"(y) : "f"(x));
    return y;
}

// Cluster of 2 CTAs per (B,C) plane; CTA rank r owns rows [128r,128r+128).
// 256 threads = 8 warps; warp w owns a 64x64 patch.
// Phase 1: (sum, sumsq, min, max) per patch. Cluster exchanges half-plane
// moments (one float2 via DSMEM). Each warp then builds a 256-interval
// piecewise-linear LUT of the full gate f(x) = basew + cf*sig2 + cm*sig1 +
// cg*sig0 over the patch's exact [min,max] (f is 1-D in x within a patch).
// Phase 2: reverse-order L2-hot re-read, LUT gate, streaming store.
__global__ __launch_bounds__(256, 7) __cluster_dims__(2, 1, 1)
void pmfm_fused(const float* __restrict__ x,
                const float* __restrict__ lw,
                float* __restrict__ out) {
    cg::cluster_group cluster = cg::this_cluster();
    const unsigned rank = cluster.block_rank();

    const int bc   = blockIdx.x >> 1;     // plane
    const int t    = threadIdx.x;
    const int w    = t >> 5;              // warp 0..7 = local patch
    const int lane = t & 31;
    const int prow = (int)rank * 2 + (w >> 2);
    const int pcol = w & 3;

    const float* plane = x + (size_t)bc * 65536;
    float* oplane      = out + (size_t)bc * 65536;
    const int colf  = pcol * 64 + (lane & 15) * 4;
    const int rbase = prow * 64 + (lane >> 4);

    const float4* pin4 = reinterpret_cast<const float4*>(plane + (size_t)rbase * 256 + colf);
    float4*       po4  = reinterpret_cast<float4*>(oplane + (size_t)rbase * 256 + colf);

    // ---- Phase 1: per-patch sum/sumsq/min/max ----
    float sA = 0.f, sB = 0.f, qA = 0.f, qB = 0.f;
    float mn = 3.4e38f, mx = -3.4e38f;
#pragma unroll
    for (int c = 0; c < 8; ++c) {
        float4 v[4];
#pragma unroll
        for (int j = 0; j < 4; ++j) v[j] = pin4[(size_t)(4 * c + j) * 128];
#pragma unroll
        for (int j = 0; j < 4; ++j) {
            float* a = (j & 1) ? &sB : &sA;
            float* q = (j & 1) ? &qB : &qA;
            *a += (v[j].x + v[j].y) + (v[j].z + v[j].w);
            *q += v[j].x * v[j].x + v[j].y * v[j].y + v[j].z * v[j].z + v[j].w * v[j].w;
            mn = fminf(mn, fminf(fminf(v[j].x, v[j].y), fminf(v[j].z, v[j].w)));
            mx = fmaxf(mx, fmaxf(fmaxf(v[j].x, v[j].y), fmaxf(v[j].z, v[j].w)));
        }
    }
    float s = sA + sB, ss = qA + qB;
#pragma unroll
    for (int o = 16; o > 0; o >>= 1) {
        s  += __shfl_xor_sync(0xffffffffu, s,  o);
        ss += __shfl_xor_sync(0xffffffffu, ss, o);
        mn  = fminf(mn, __shfl_xor_sync(0xffffffffu, mn, o));
        mx  = fmaxf(mx, __shfl_xor_sync(0xffffffffu, mx, o));
    }
    __shared__ float4 st4[8];       // (sum, sumsq, min, max) per local patch
    __shared__ float2 sh_half;      // this CTA's half-plane (sum, sumsq)
    __shared__ float2 tab[8 * 256]; // per-warp LUT: (f_i, f_{i+1}-f_i)
    if (lane == 0) st4[w] = make_float4(s, ss, mn, mx);
    __syncthreads();
    if (t < 8) {
        float hs = st4[t].x, hq = st4[t].y;
#pragma unroll
        for (int o = 4; o > 0; o >>= 1) {
            hs += __shfl_xor_sync(0x000000ffu, hs, o, 8);
            hq += __shfl_xor_sync(0x000000ffu, hq, o, 8);
        }
        if (t == 0) sh_half = make_float2(hs, hq);
    }
    cluster.sync();

    // ---- Peer half-plane moments via DSMEM ----
    float ph_s, ph_q;
    {
        float2 ph = make_float2(0.f, 0.f);
        if (lane == 0) {
            const float2* peer = (const float2*)cluster.map_shared_rank(
                (void*)&sh_half, rank ^ 1u);
            ph = *peer;
        }
        ph_s = __shfl_sync(0xffffffffu, ph.x, 0);  // forces DSMEM read complete
        ph_q = __shfl_sync(0xffffffffu, ph.y, 0);
    }
    const float2 own_half = sh_half;
    const float4 f2 = st4[w];
    float s1 = 0.f, q1 = 0.f;       // level 1: 2x2 quadrant (CTA-local)
    {
        const int qc = pcol & ~1;
#pragma unroll
        for (int dr = 0; dr < 2; ++dr)
#pragma unroll
            for (int dc = 0; dc < 2; ++dc) {
                const float4 v = st4[dr * 4 + (qc + dc)];
                s1 += v.x; q1 += v.y;
            }
    }
    const float s0 = own_half.x + ph_s;
    const float q0 = own_half.y + ph_q;

    // Early arrive: done reading peer smem; matching wait at kernel end.
    asm volatile("barrier.cluster.arrive.aligned;" ::: "memory");

    const float iN2 = 1.f / 4096.f, iN1 = 1.f / 16384.f, iN0 = 1.f / 65536.f;
    const float mu2 = f2.x * iN2; const float v2 = fmaxf(f2.y * iN2 - mu2 * mu2, 0.f);
    const float mu1 = s1  * iN1; const float v1 = fmaxf(q1  * iN1 - mu1 * mu1, 0.f);
    const float mu0 = s0  * iN0; const float v0 = fmaxf(q0  * iN0 - mu0 * mu0, 0.f);

    const float a2 = 0.5f * rsqrtf(v2 + EPS), b2 = -mu2 * a2;
    const float a1 = 0.5f * rsqrtf(v1 + EPS), b1 = -mu1 * a1;
    const float a0 = 0.5f * rsqrtf(v0 + EPS), b0 = -mu0 * a0;

    const float w0 = __ldg(lw + 0), w1 = __ldg(lw + 1), w2 = __ldg(lw + 2);
    const float m  = fmaxf(w0, fmaxf(w1, w2));
    const float e0 = __expf(w0 - m), e1 = __expf(w1 - m), e2 = __expf(w2 - m);
    const float cc = (1.f - THETA) * 0.5f / (e0 + e1 + e2);
    const float cf = cc * e0, cm = cc * e1, cg_ = cc * e2;
    const float basew = THETA + (1.f - THETA) * 0.5f;

    // ---- Build per-patch LUT of f(x) over [mn, mx], 256 intervals ----
    const float lo = f2.z, hi = f2.w;
    const float h    = (hi - lo) * (1.f / 256.f);
    const float invh = 256.f / (hi - lo);          // may be inf if hi==lo
    float2* mytab = &tab[w << 8];
#pragma unroll
    for (int k = 0; k < 8; ++k) {
        const int i = lane + (k << 5);
        const float xi  = fmaf((float)i,       h, lo);
        const float xi1 = fmaf((float)(i + 1), h, lo);
        const float fi  = fmaf(cf, fast_tanh(fmaf(xi,  a2, b2)),
                          fmaf(cm, fast_tanh(fmaf(xi,  a1, b1)),
                          fmaf(cg_, fast_tanh(fmaf(xi,  a0, b0)), basew)));
        const float fi1 = fmaf(cf, fast_tanh(fmaf(xi1, a2, b2)),
                          fmaf(cm, fast_tanh(fmaf(xi1, a1, b1)),
                          fmaf(cg_, fast_tanh(fmaf(xi1, a0, b0)), basew)));
        mytab[i] = make_float2(fi, fi1 - fi);
    }
    __syncwarp();

    // ---- Phase 2: reverse L2-hot re-read, LUT gate, streaming store ----
    const float nlo = -lo * invh;
#pragma unroll
    for (int ch = 7; ch >= 0; --ch) {
        float4 v[4];
#pragma unroll
        for (int j = 0; j < 4; ++j)
            v[j] = __ldcs(&pin4[(size_t)(4 * ch + 3 - j) * 128]);
#pragma unroll
        for (int j = 0; j < 4; ++j) {
            float4 res;
#define PMFM_DO(comp)                                                     \
            {                                                             \
                const float xx = v[j].comp;                               \
                float u = fmaf(xx, invh, nlo);                            \
                u = fminf(fmaxf(u, 0.f), 255.999f);  /* NaN (h=0) -> 0 */ \
                const float ff = floorf(u);                               \
                const float2 e = mytab[(int)ff];                          \
                res.comp = xx * fmaf(e.y, u - ff, e.x);                   \
            }
            PMFM_DO(x) PMFM_DO(y) PMFM_DO(z) PMFM_DO(w)
#undef PMFM_DO
            __stcs(&po4[(size_t)(4 * ch + 3 - j) * 128], res);
        }
    }

    // No CTA exits while its peer might still read sh_half.
    asm volatile("barrier.cluster.wait.aligned;" ::: "memory");
}

extern "C" void kernel_launch(void* const* d_in, const int* in_sizes, int n_in,
                              void* d_out, int out_size) {
    const float* x;
    const float* lw;
    long nx;
    if (in_sizes[0] >= in_sizes[1]) {
        x = (const float*)d_in[0]; lw = (const float*)d_in[1]; nx = in_sizes[0];
    } else {
        x = (const float*)d_in[1]; lw = (const float*)d_in[0]; nx = in_sizes[1];
    }
    const int nplanes = (int)(nx / 65536);   // B*C = 512 planes of 256x256
    pmfm_fused<<<nplanes * 2, 256>>>(x, lw, (float*)d_out);
}

// round 7
// speedup vs baseline: 1.0315x; 1.0315x over previous
#include <cuda_runtime.h>
#include <cooperative_groups.h>
namespace cg = cooperative_groups;

#define THETA 0.5f
#define EPS   1e-5f

__device__ __forceinline__ float fast_tanh(float x) {
    float y;
    asm("tanh.approx.f32 %0, %1;" : "=f"(y) : "f"(x));
    return y;
}

// Cluster of 2 CTAs per (B,C) plane; CTA rank r owns rows [128r, 128r+128).
// 512 threads = 16 warps; warp pair (2p, 2p+1) owns 64x64 patch p (0..7).
// Each thread loads its 16 float4 ONCE into registers (MLP=16), reduces
// (sum,sumsq), exchanges the half-plane moment with the peer CTA via DSMEM,
// then gates straight from registers and streams out. No second read.
__global__ __launch_bounds__(512, 1) __cluster_dims__(2, 1, 1)
void pmfm_fused(const float* __restrict__ x,
                const float* __restrict__ lw,
                float* __restrict__ out) {
    cg::cluster_group cluster = cg::this_cluster();
    const unsigned rank = cluster.block_rank();

    const int bc   = blockIdx.x >> 1;     // plane
    const int t    = threadIdx.x;
    const int w    = t >> 5;              // warp 0..15
    const int lane = t & 31;
    const int p    = w >> 1;              // local patch 0..7
    const int prl  = p >> 2;              // local patch row 0..1
    const int pcol = p & 3;

    const float* plane = x + (size_t)bc * 65536;
    float* oplane      = out + (size_t)bc * 65536;
    const int colf = pcol * 64 + (lane & 15) * 4;
    // row within patch: (lane>>4) + 2*(w&1) + 4k, k=0..15
    const int r0   = (lane >> 4) + ((w & 1) << 1);
    const int grow = (int)rank * 128 + prl * 64 + r0;

    const float4* pin4 = reinterpret_cast<const float4*>(plane + (size_t)grow * 256 + colf);
    float4*       po4  = reinterpret_cast<float4*>(oplane + (size_t)grow * 256 + colf);

    // ---- Phase 1: single read into registers (batched: max MLP) ----
    float4 v[16];
#pragma unroll
    for (int k = 0; k < 16; ++k)
        v[k] = __ldcs(&pin4[(size_t)k * 256]);   // stride 4 rows

    float sA = 0.f, sB = 0.f, qA = 0.f, qB = 0.f;
#pragma unroll
    for (int k = 0; k < 16; k += 2) {
        sA += (v[k].x + v[k].y) + (v[k].z + v[k].w);
        qA += v[k].x * v[k].x + v[k].y * v[k].y + v[k].z * v[k].z + v[k].w * v[k].w;
        sB += (v[k+1].x + v[k+1].y) + (v[k+1].z + v[k+1].w);
        qB += v[k+1].x * v[k+1].x + v[k+1].y * v[k+1].y + v[k+1].z * v[k+1].z + v[k+1].w * v[k+1].w;
    }
    float s = sA + sB, ss = qA + qB;
#pragma unroll
    for (int o = 16; o > 0; o >>= 1) {
        s  += __shfl_xor_sync(0xffffffffu, s,  o);
        ss += __shfl_xor_sync(0xffffffffu, ss, o);
    }

    __shared__ float2 stw[16];      // per-warp partials
    __shared__ float2 sh_half;      // this CTA's half-plane (sum, sumsq)
    if (lane == 0) stw[w] = make_float2(s, ss);
    __syncthreads();
    if (t < 16) {                   // reduce 16 warp partials -> half total
        float hs = stw[t].x, hq = stw[t].y;
#pragma unroll
        for (int o = 8; o > 0; o >>= 1) {
            hs += __shfl_xor_sync(0x0000ffffu, hs, o, 16);
            hq += __shfl_xor_sync(0x0000ffffu, hq, o, 16);
        }
        if (t == 0) sh_half = make_float2(hs, hq);
    }
    cluster.sync();                 // stw + sh_half visible cluster-wide

    // ---- Peer half-plane moments via DSMEM (one float2) ----
    float ph_s, ph_q;
    {
        float2 ph = make_float2(0.f, 0.f);
        if (lane == 0) {
            const float2* peer = (const float2*)cluster.map_shared_rank(
                (void*)&sh_half, rank ^ 1u);
            ph = *peer;
        }
        ph_s = __shfl_sync(0xffffffffu, ph.x, 0);  // forces DSMEM read done
        ph_q = __shfl_sync(0xffffffffu, ph.y, 0);
    }
    const float2 own_half = sh_half;
    // level 2: own patch = warp pair (2p, 2p+1)
    const float2 e0p = stw[2 * p], e1p = stw[2 * p + 1];
    const float f2s = e0p.x + e1p.x, f2q = e0p.y + e1p.y;
    // level 1: 2x2 patch quadrant (CTA-local: both patch rows live here)
    float s1 = 0.f, q1 = 0.f;
    {
        const int qc = pcol & ~1;
#pragma unroll
        for (int dr = 0; dr < 2; ++dr)
#pragma unroll
            for (int dc = 0; dc < 2; ++dc) {
                const int pp = dr * 4 + (qc + dc);
                s1 += stw[2 * pp].x + stw[2 * pp + 1].x;
                q1 += stw[2 * pp].y + stw[2 * pp + 1].y;
            }
    }
    const float s0 = own_half.x + ph_s;            // level 0: whole plane
    const float q0 = own_half.y + ph_q;

    // Early arrive: done reading peer smem; matching wait at kernel end.
    asm volatile("barrier.cluster.arrive.aligned;" ::: "memory");

    const float iN2 = 1.f / 4096.f, iN1 = 1.f / 16384.f, iN0 = 1.f / 65536.f;
    const float mu2 = f2s * iN2; const float v2 = fmaxf(f2q * iN2 - mu2 * mu2, 0.f);
    const float mu1 = s1  * iN1; const float v1 = fmaxf(q1  * iN1 - mu1 * mu1, 0.f);
    const float mu0 = s0  * iN0; const float v0 = fmaxf(q0  * iN0 - mu0 * mu0, 0.f);

    // sigmoid(z) = 0.5 + 0.5*tanh(z/2); arg = x*a + b, a = 0.5*rsig, b = -mu*a
    const float a2 = 0.5f * rsqrtf(v2 + EPS), b2 = -mu2 * a2;
    const float a1 = 0.5f * rsqrtf(v1 + EPS), b1 = -mu1 * a1;
    const float a0 = 0.5f * rsqrtf(v0 + EPS), b0 = -mu0 * a0;

    // softmax(level_weights); lw[0] pairs with p=2 (finest), lw[2] with p=0
    const float w0 = __ldg(lw + 0), w1 = __ldg(lw + 1), w2 = __ldg(lw + 2);
    const float mmax = fmaxf(w0, fmaxf(w1, w2));
    const float ew0 = __expf(w0 - mmax), ew1 = __expf(w1 - mmax), ew2 = __expf(w2 - mmax);
    const float cc = (1.f - THETA) * 0.5f / (ew0 + ew1 + ew2);
    const float cf = cc * ew0, cm = cc * ew1, cg_ = cc * ew2;
    const float basew = THETA + (1.f - THETA) * 0.5f;

    // ---- Phase 2: gate from registers, streaming store ----
#pragma unroll
    for (int k = 0; k < 16; ++k) {
        float4 res;
#define PMFM_DO(comp)                                                          \
        {                                                                      \
            const float xx = v[k].comp;                                        \
            const float tf = fast_tanh(fmaf(xx, a2, b2));                      \
            const float tm = fast_tanh(fmaf(xx, a1, b1));                      \
            const float tg = fast_tanh(fmaf(xx, a0, b0));                      \
            const float f  = fmaf(cf, tf, fmaf(cm, tm, fmaf(cg_, tg, basew))); \
            res.comp = xx * f;                                                 \
        }
        PMFM_DO(x) PMFM_DO(y) PMFM_DO(z) PMFM_DO(w)
#undef PMFM_DO
        __stcs(&po4[(size_t)k * 256], res);
    }

    // No CTA exits while its peer might still read sh_half.
    asm volatile("barrier.cluster.wait.aligned;" ::: "memory");
}

extern "C" void kernel_launch(void* const* d_in, const int* in_sizes, int n_in,
                              void* d_out, int out_size) {
    const float* x;
    const float* lw;
    long nx;
    if (in_sizes[0] >= in_sizes[1]) {
        x = (const float*)d_in[0]; lw = (const float*)d_in[1]; nx = in_sizes[0];
    } else {
        x = (const float*)d_in[1]; lw = (const float*)d_in[0]; nx = in_sizes[1];
    }
    const int nplanes = (int)(nx / 65536);   // B*C = 512 planes of 256x256
    pmfm_fused<<<nplanes * 2, 512>>>(x, lw, (float*)d_out);
}

// round 8
// speedup vs baseline: 1.1026x; 1.0689x over previous
#include <cuda_runtime.h>
#include <cooperative_groups.h>
namespace cg = cooperative_groups;

#define THETA 0.5f
#define EPS   1e-5f

__device__ __forceinline__ float fast_tanh(float x) {
    float y;
    asm("tanh.approx.f32 %0, %1;" : "=f"(y) : "f"(x));
    return y;
}

// Cluster of 2 CTAs per (B,C) plane; CTA rank r owns rows [128r, 128r+128).
// 256 threads = 8 warps; warp w owns 64x64 patch (prow = 2r + (w>>2), pcol = w&3).
// Phase 1: 4-deep batched loads -> per-patch (sum,sumsq); half-plane moment
// exchanged with peer CTA via DSMEM (one float2). Phase 2: reverse-order
// L2-hot re-read, software-pipelined (double-buffered 2x float4 chunks) so the
// L2 latency hides under tanh/FMA work. 8 CTAs/SM (full occupancy).
__global__ __launch_bounds__(256, 8) __cluster_dims__(2, 1, 1)
void pmfm_fused(const float* __restrict__ x,
                const float* __restrict__ lw,
                float* __restrict__ out) {
    cg::cluster_group cluster = cg::this_cluster();
    const unsigned rank = cluster.block_rank();

    const int bc   = blockIdx.x >> 1;     // plane
    const int t    = threadIdx.x;
    const int w    = t >> 5;              // warp 0..7 = local patch
    const int lane = t & 31;
    const int prow = (int)rank * 2 + (w >> 2);
    const int pcol = w & 3;

    const float* plane = x + (size_t)bc * 65536;
    float* oplane      = out + (size_t)bc * 65536;
    const int colf  = pcol * 64 + (lane & 15) * 4;
    const int rbase = prow * 64 + (lane >> 4);      // start row (stride 2)

    const float4* pin4 = reinterpret_cast<const float4*>(plane + (size_t)rbase * 256 + colf);
    float4*       po4  = reinterpret_cast<float4*>(oplane + (size_t)rbase * 256 + colf);

    // ---- Phase 1: per-patch moments, 4-deep batches, dual accumulators ----
    float sA = 0.f, sB = 0.f, qA = 0.f, qB = 0.f;
#pragma unroll
    for (int c = 0; c < 8; ++c) {
        const float4 va = pin4[(size_t)(4 * c + 0) * 128];
        const float4 vb = pin4[(size_t)(4 * c + 1) * 128];
        const float4 vc = pin4[(size_t)(4 * c + 2) * 128];
        const float4 vd = pin4[(size_t)(4 * c + 3) * 128];
        sA += (va.x + va.y) + (va.z + va.w);
        qA += va.x * va.x + va.y * va.y + va.z * va.z + va.w * va.w;
        sB += (vb.x + vb.y) + (vb.z + vb.w);
        qB += vb.x * vb.x + vb.y * vb.y + vb.z * vb.z + vb.w * vb.w;
        sA += (vc.x + vc.y) + (vc.z + vc.w);
        qA += vc.x * vc.x + vc.y * vc.y + vc.z * vc.z + vc.w * vc.w;
        sB += (vd.x + vd.y) + (vd.z + vd.w);
        qB += vd.x * vd.x + vd.y * vd.y + vd.z * vd.z + vd.w * vd.w;
    }
    float s = sA + sB, ss = qA + qB;
#pragma unroll
    for (int o = 16; o > 0; o >>= 1) {
        s  += __shfl_xor_sync(0xffffffffu, s,  o);
        ss += __shfl_xor_sync(0xffffffffu, ss, o);
    }
    __shared__ float2 st[8];        // local 8 patch stats
    __shared__ float2 sh_half;      // this CTA's half-plane total
    if (lane == 0) st[w] = make_float2(s, ss);
    __syncthreads();
    if (t < 8) {
        float2 v = st[t];
        float hs = v.x, hq = v.y;
#pragma unroll
        for (int o = 4; o > 0; o >>= 1) {
            hs += __shfl_xor_sync(0x000000ffu, hs, o, 8);
            hq += __shfl_xor_sync(0x000000ffu, hq, o, 8);
        }
        if (t == 0) sh_half = make_float2(hs, hq);
    }
    cluster.sync();

    // ---- Peer half-plane total via DSMEM (lane 0 loads, warp broadcast) ----
    float ph_s, ph_q;
    {
        float2 ph = make_float2(0.f, 0.f);
        if (lane == 0) {
            const float2* peer = (const float2*)cluster.map_shared_rank(
                (void*)&sh_half, rank ^ 1u);
            ph = *peer;
        }
        ph_s = __shfl_sync(0xffffffffu, ph.x, 0);  // forces DSMEM read done
        ph_q = __shfl_sync(0xffffffffu, ph.y, 0);
    }
    const float2 own_half = sh_half;
    const float2 f2 = st[w];                        // level 2: own patch
    float s1 = 0.f, q1 = 0.f;                       // level 1: 2x2 quadrant
    {
        const int qc = pcol & ~1;
#pragma unroll
        for (int dr = 0; dr < 2; ++dr)
#pragma unroll
            for (int dc = 0; dc < 2; ++dc) {
                const float2 v = st[dr * 4 + (qc + dc)];
                s1 += v.x; q1 += v.y;
            }
    }
    const float s0 = own_half.x + ph_s;             // level 0: whole plane
    const float q0 = own_half.y + ph_q;

    // Early arrive; matching wait at kernel end overlaps with phase 2.
    asm volatile("barrier.cluster.arrive.aligned;" ::: "memory");

    const float iN2 = 1.f / 4096.f, iN1 = 1.f / 16384.f, iN0 = 1.f / 65536.f;
    const float mu2 = f2.x * iN2; const float v2 = fmaxf(f2.y * iN2 - mu2 * mu2, 0.f);
    const float mu1 = s1  * iN1; const float v1 = fmaxf(q1  * iN1 - mu1 * mu1, 0.f);
    const float mu0 = s0  * iN0; const float v0 = fmaxf(q0  * iN0 - mu0 * mu0, 0.f);

    const float a2 = 0.5f * rsqrtf(v2 + EPS), b2 = -mu2 * a2;
    const float a1 = 0.5f * rsqrtf(v1 + EPS), b1 = -mu1 * a1;
    const float a0 = 0.5f * rsqrtf(v0 + EPS), b0 = -mu0 * a0;

    const float w0 = __ldg(lw + 0), w1 = __ldg(lw + 1), w2 = __ldg(lw + 2);
    const float m  = fmaxf(w0, fmaxf(w1, w2));
    const float e0 = __expf(w0 - m), e1 = __expf(w1 - m), e2 = __expf(w2 - m);
    const float cc = (1.f - THETA) * 0.5f / (e0 + e1 + e2);
    const float cf = cc * e0, cm = cc * e1, cg_ = cc * e2;
    const float basew = THETA + (1.f - THETA) * 0.5f;

    // ---- Phase 2: reverse L2-hot re-read, software-pipelined ----
    // chunks of 2 float4, double-buffered: loads for chunk c-1 are issued
    // before computing chunk c, hiding L2 latency under tanh/FMA work.
    float4 buf[2][2];
    buf[1][0] = __ldcs(&pin4[(size_t)(2 * 15 + 0) * 128]);
    buf[1][1] = __ldcs(&pin4[(size_t)(2 * 15 + 1) * 128]);
#pragma unroll
    for (int c = 15; c >= 0; --c) {
        if (c > 0) {
            buf[(c - 1) & 1][0] = __ldcs(&pin4[(size_t)(2 * (c - 1) + 0) * 128]);
            buf[(c - 1) & 1][1] = __ldcs(&pin4[(size_t)(2 * (c - 1) + 1) * 128]);
        }
        float4* cur = buf[c & 1];
#pragma unroll
        for (int j = 0; j < 2; ++j) {
            float4 res;
#define PMFM_DO(comp)                                                          \
            {                                                                  \
                const float xx = cur[j].comp;                                  \
                const float tf = fast_tanh(fmaf(xx, a2, b2));                  \
                const float tm = fast_tanh(fmaf(xx, a1, b1));                  \
                const float tg = fast_tanh(fmaf(xx, a0, b0));                  \
                const float f  = fmaf(cf, tf, fmaf(cm, tm, fmaf(cg_, tg, basew))); \
                res.comp = xx * f;                                             \
            }
            PMFM_DO(x) PMFM_DO(y) PMFM_DO(z) PMFM_DO(w)
#undef PMFM_DO
            __stcs(&po4[(size_t)(2 * c + j) * 128], res);
        }
    }

    // No CTA exits while its peer might still read sh_half.
    asm volatile("barrier.cluster.wait.aligned;" ::: "memory");
}

extern "C" void kernel_launch(void* const* d_in, const int* in_sizes, int n_in,
                              void* d_out, int out_size) {
    const float* x;
    const float* lw;
    long nx;
    if (in_sizes[0] >= in_sizes[1]) {
        x = (const float*)d_in[0]; lw = (const float*)d_in[1]; nx = in_sizes[0];
    } else {
        x = (const float*)d_in[1]; lw = (const float*)d_in[0]; nx = in_sizes[1];
    }
    const int nplanes = (int)(nx / 65536);   // B*C = 512 planes of 256x256
    pmfm_fused<<<nplanes * 2, 256>>>(x, lw, (float*)d_out);
}